// round 1
// baseline (speedup 1.0000x reference)
#include <cuda_runtime.h>
#include <stdint.h>

// Problem shape (fixed by the dataset)
#define BATCH   8192
#define IN_DIM  4096
#define N_RULES 2048
#define KWORDS  (IN_DIM / 32)   // 128 x u32 bit-words along k

// Scratch (device globals — no allocation allowed in kernel_launch)
__device__ uint32_t g_wbits[N_RULES * KWORDS];  // [r][w]: bit j = (W[w*32+j, r] > 0.5)
__device__ uint32_t g_abits[BATCH   * KWORDS];  // [b][w]: bit j = (x[b, w*32+j] != 1.0f)
__device__ uint32_t g_wany [N_RULES];           // OR of all Wbits words for rule r
__device__ uint32_t g_aflag[BATCH];             // 1 if row b has any x == 1.0f exactly

// ---------------------------------------------------------------------------
// Kernel 1: pack W > 0.5 into bits. Warp lanes map to consecutive rules r so
// each k-iteration is a fully coalesced 128B load of W[k, r..r+31].
// ---------------------------------------------------------------------------
__global__ void pack_w_kernel(const float* __restrict__ W) {
    int idx = blockIdx.x * blockDim.x + threadIdx.x;   // [0, N_RULES*KWORDS)
    int r = idx & (N_RULES - 1);
    int w = idx >> 11;                                  // log2(N_RULES)=11
    const float* p = W + (size_t)(w * 32) * N_RULES + r;
    uint32_t word = 0;
#pragma unroll
    for (int j = 0; j < 32; j++) {
        if (p[(size_t)j * N_RULES] > 0.5f) word |= (1u << j);
    }
    g_wbits[r * KWORDS + w] = word;
}

// ---------------------------------------------------------------------------
// Kernel 2: pack (x != 1.0f) into bits via ballot. One lane per element:
// fully coalesced reads of x; lane 0 of each 32-element group writes one word.
// ---------------------------------------------------------------------------
__global__ void pack_x_kernel(const float* __restrict__ x) {
    int idx = blockIdx.x * blockDim.x + threadIdx.x;    // [0, BATCH*IN_DIM)
    float v = x[idx];
    unsigned mask = __ballot_sync(0xFFFFFFFFu, v != 1.0f);
    if ((threadIdx.x & 31) == 0) {
        g_abits[idx >> 5] = mask;   // (b*IN_DIM + col)/32 == b*KWORDS + col/32
    }
}

// ---------------------------------------------------------------------------
// Kernel 3: summaries. wany[r] = OR of rule r's words (rule has any active
// weight); aflag[b] = row b contains an exact x==1.0 (some A-bit is 0).
// ---------------------------------------------------------------------------
__global__ void reduce_masks_kernel() {
    int t = blockIdx.x * blockDim.x + threadIdx.x;
    if (t < N_RULES) {
        const uint4* p = reinterpret_cast<const uint4*>(g_wbits + t * KWORDS);
        uint32_t o = 0;
#pragma unroll 8
        for (int i = 0; i < KWORDS / 4; i++) {
            uint4 v = p[i];
            o |= v.x | v.y | v.z | v.w;
        }
        g_wany[t] = o;
    } else if (t < N_RULES + BATCH) {
        int b = t - N_RULES;
        const uint4* p = reinterpret_cast<const uint4*>(g_abits + b * KWORDS);
        uint32_t a = 0xFFFFFFFFu;
#pragma unroll 8
        for (int i = 0; i < KWORDS / 4; i++) {
            uint4 v = p[i];
            a &= v.x & v.y & v.z & v.w;
        }
        g_aflag[b] = (a != 0xFFFFFFFFu) ? 1u : 0u;
    }
}

// Rare general path: any weight-selected k with x[b,k] != 1 makes res > 0.
__device__ __forceinline__ float conj_general(int b, int r) {
    const uint32_t* A  = g_abits + b * KWORDS;
    const uint32_t* Wp = g_wbits + r * KWORDS;
    for (int i = 0; i < KWORDS; i++) {
        if (A[i] & Wp[i]) return 0.0f;
    }
    return 1.0f;
}

// ---------------------------------------------------------------------------
// Kernel 4: output [BATCH, N_RULES] f32, float4-vectorized (4 rules/thread).
// Fast paths: empty rule -> 1.0; no exact-1 x in row -> 0.0 for nonempty rule.
// ---------------------------------------------------------------------------
__global__ void out_kernel(float* __restrict__ out) {
    int idx = blockIdx.x * blockDim.x + threadIdx.x;    // [0, BATCH * N_RULES/4)
    const int GPR = N_RULES / 4;                        // 512 groups per row
    int b = idx / GPR;
    int g = idx - b * GPR;
    uint4 w4 = reinterpret_cast<const uint4*>(g_wany)[g];
    uint32_t af = g_aflag[b];

    float4 o;
    if ((w4.x | w4.y | w4.z | w4.w) == 0u) {
        // all 4 rules empty -> res == 0 -> output 1 (dominant case)
        o = make_float4(1.0f, 1.0f, 1.0f, 1.0f);
    } else if (!af) {
        // row has no exact x==1: nonempty rule -> res > 0 -> 0
        o.x = (w4.x == 0u) ? 1.0f : 0.0f;
        o.y = (w4.y == 0u) ? 1.0f : 0.0f;
        o.z = (w4.z == 0u) ? 1.0f : 0.0f;
        o.w = (w4.w == 0u) ? 1.0f : 0.0f;
    } else {
        int r0 = g * 4;
        o.x = (w4.x == 0u) ? 1.0f : conj_general(b, r0 + 0);
        o.y = (w4.y == 0u) ? 1.0f : conj_general(b, r0 + 1);
        o.z = (w4.z == 0u) ? 1.0f : conj_general(b, r0 + 2);
        o.w = (w4.w == 0u) ? 1.0f : conj_general(b, r0 + 3);
    }
    reinterpret_cast<float4*>(out)[idx] = o;
}

// ---------------------------------------------------------------------------
extern "C" void kernel_launch(void* const* d_in, const int* in_sizes, int n_in,
                              void* d_out, int out_size) {
    const float* x = (const float*)d_in[0];   // [BATCH, IN_DIM]
    const float* W = (const float*)d_in[1];   // [IN_DIM, N_RULES]
    float* out = (float*)d_out;               // [BATCH, N_RULES]

    (void)in_sizes; (void)n_in; (void)out_size;

    {   // pack W
        int total = N_RULES * KWORDS;         // 262144
        pack_w_kernel<<<total / 256, 256>>>(W);
    }
    {   // pack x
        long long total = (long long)BATCH * IN_DIM;   // 33.5M
        pack_x_kernel<<<(int)(total / 256), 256>>>(x);
    }
    {   // summaries
        int total = N_RULES + BATCH;          // 10240
        reduce_masks_kernel<<<(total + 255) / 256, 256>>>();
    }
    {   // output
        int total = BATCH * (N_RULES / 4);    // 4.19M threads
        out_kernel<<<total / 256, 256>>>(out);
    }
}

// round 2
// speedup vs baseline: 1.9460x; 1.9460x over previous
#include <cuda_runtime.h>
#include <stdint.h>

// Problem shape (fixed by the dataset)
#define BATCH   8192
#define IN_DIM  4096
#define N_RULES 2048
#define KWORDS  (IN_DIM / 32)   // 128 u32 bit-words along k

// Scratch (device globals — no allocation allowed)
__device__ uint32_t g_wbits[N_RULES * KWORDS];  // [r][w]: bit j = (W[w*32+j, r] > 0.5)
__device__ uint32_t g_abits[BATCH   * KWORDS];  // [b][w]: bit j = (x[b, w*32+j] != 1.0f)
__device__ uint32_t g_wany [N_RULES];           // OR of rule r's words
__device__ uint32_t g_aflag[BATCH];             // 1 if row b has any exact x == 1.0f

// ---------------------------------------------------------------------------
// Kernel 0: zero the summary flags (graph replays require re-init).
// ---------------------------------------------------------------------------
__global__ void init_flags_kernel() {
    int t = blockIdx.x * blockDim.x + threadIdx.x;
    if (t < N_RULES) g_wany[t] = 0u;
    int b = t - N_RULES;
    if (b >= 0 && b < BATCH) g_aflag[b] = 0u;
}

// ---------------------------------------------------------------------------
// Kernel 1: pack W > 0.5 into bits + fused wany accumulation.
// Warp lanes map to consecutive rules r -> each of the 32 k-loads is a fully
// coalesced 128B transaction. atomicOr fires only if the rule is non-empty
// (never on this data distribution: W in [0, 0.5)).
// ---------------------------------------------------------------------------
__global__ void pack_w_kernel(const float* __restrict__ W) {
    int idx = blockIdx.x * blockDim.x + threadIdx.x;   // [0, N_RULES*KWORDS)
    int r = idx & (N_RULES - 1);
    int w = idx >> 11;                                  // log2(N_RULES) = 11
    const float* p = W + (size_t)(w * 32) * N_RULES + r;
    uint32_t word = 0;
#pragma unroll
    for (int j = 0; j < 32; j++) {
        if (p[(size_t)j * N_RULES] > 0.5f) word |= (1u << j);
    }
    g_wbits[r * KWORDS + w] = word;
    if (word) atomicOr(&g_wany[r], word);
}

// ---------------------------------------------------------------------------
// Kernel 2: pack (x != 1.0f) into bits, one 32-bit word per thread via
// 8 x float4 loads (MLP=8), + fused aflag. atomicOr fires only if the row
// contains an exact 1.0 (never for x ~ U[0,1)).
// ---------------------------------------------------------------------------
__global__ void pack_x_kernel(const float* __restrict__ x) {
    int idx = blockIdx.x * blockDim.x + threadIdx.x;    // [0, BATCH*KWORDS)
    const float4* p = reinterpret_cast<const float4*>(x) + idx * 8;
    uint32_t word = 0;
#pragma unroll
    for (int i = 0; i < 8; i++) {
        float4 v = p[i];
        uint32_t nib = 0;
        nib |= (v.x != 1.0f) ? 1u : 0u;
        nib |= (v.y != 1.0f) ? 2u : 0u;
        nib |= (v.z != 1.0f) ? 4u : 0u;
        nib |= (v.w != 1.0f) ? 8u : 0u;
        word |= nib << (i * 4);
    }
    g_abits[idx] = word;
    if (word != 0xFFFFFFFFu) atomicOr(&g_aflag[idx >> 7], 1u);  // idx/KWORDS = b
}

// Rare general path: any weight-selected k with x[b,k] != 1 makes res > 0.
__device__ __forceinline__ float conj_general(int b, int r) {
    const uint32_t* A  = g_abits + b * KWORDS;
    const uint32_t* Wp = g_wbits + r * KWORDS;
    for (int i = 0; i < KWORDS; i++) {
        if (A[i] & Wp[i]) return 0.0f;
    }
    return 1.0f;
}

// ---------------------------------------------------------------------------
// Kernel 3: output [BATCH, N_RULES] f32, float4-vectorized (4 rules/thread).
// Fast paths: empty rule -> 1.0; no exact-1 x in row -> 0.0 for nonempty rule.
// ---------------------------------------------------------------------------
__global__ void out_kernel(float* __restrict__ out) {
    int idx = blockIdx.x * blockDim.x + threadIdx.x;    // [0, BATCH * N_RULES/4)
    const int GPR = N_RULES / 4;                        // 512 groups per row
    int b = idx >> 9;                                   // idx / GPR
    int g = idx & (GPR - 1);
    uint4 w4 = reinterpret_cast<const uint4*>(g_wany)[g];

    float4 o;
    if ((w4.x | w4.y | w4.z | w4.w) == 0u) {
        // all 4 rules empty -> res == 0 -> output 1 (dominant case)
        o = make_float4(1.0f, 1.0f, 1.0f, 1.0f);
    } else if (!g_aflag[b]) {
        // row has no exact x==1: any nonempty rule -> res > 0 -> 0
        o.x = (w4.x == 0u) ? 1.0f : 0.0f;
        o.y = (w4.y == 0u) ? 1.0f : 0.0f;
        o.z = (w4.z == 0u) ? 1.0f : 0.0f;
        o.w = (w4.w == 0u) ? 1.0f : 0.0f;
    } else {
        int r0 = g * 4;
        o.x = (w4.x == 0u) ? 1.0f : conj_general(b, r0 + 0);
        o.y = (w4.y == 0u) ? 1.0f : conj_general(b, r0 + 1);
        o.z = (w4.z == 0u) ? 1.0f : conj_general(b, r0 + 2);
        o.w = (w4.w == 0u) ? 1.0f : conj_general(b, r0 + 3);
    }
    reinterpret_cast<float4*>(out)[idx] = o;
}

// ---------------------------------------------------------------------------
extern "C" void kernel_launch(void* const* d_in, const int* in_sizes, int n_in,
                              void* d_out, int out_size) {
    const float* x = (const float*)d_in[0];   // [BATCH, IN_DIM]
    const float* W = (const float*)d_in[1];   // [IN_DIM, N_RULES]
    float* out = (float*)d_out;               // [BATCH, N_RULES]

    (void)in_sizes; (void)n_in; (void)out_size;

    {   // zero summary flags
        int total = N_RULES + BATCH;                 // 10240
        init_flags_kernel<<<(total + 255) / 256, 256>>>();
    }
    {   // pack W (+ fused wany)
        int total = N_RULES * KWORDS;                // 262144
        pack_w_kernel<<<total / 256, 256>>>(W);
    }
    {   // pack x (+ fused aflag): one word (32 floats) per thread
        int total = BATCH * KWORDS;                  // 1,048,576
        pack_x_kernel<<<total / 256, 256>>>(x);
    }
    {   // output
        int total = BATCH * (N_RULES / 4);           // 4,194,304 threads
        out_kernel<<<total / 256, 256>>>(out);
    }
}

// round 3
// speedup vs baseline: 2.1882x; 1.1245x over previous
#include <cuda_runtime.h>
#include <stdint.h>

// Problem shape (fixed by the dataset)
#define BATCH   8192
#define IN_DIM  4096
#define N_RULES 2048
#define KWORDS  (IN_DIM / 32)     // 128 u32 bit-words along k
#define NSPLIT  4                 // k-splits for pack_w (wany partials)
#define WBLOCKS (NSPLIT * (N_RULES / 32))   // 256 pack_w blocks

// Scratch (device globals — no allocation allowed)
__device__ uint32_t g_wbits[N_RULES * KWORDS];     // [r][w]
__device__ uint32_t g_abits[BATCH   * KWORDS];     // [b][w]
__device__ uint32_t g_wany4[NSPLIT * N_RULES];     // per-split OR of rule words
__device__ uint32_t g_aflag[BATCH];                // 1 if row b has any exact x==1.0f

// ---------------------------------------------------------------------------
// Fused pack kernel. Blocks [0, WBLOCKS) pack W; blocks [WBLOCKS, +BATCH) pack
// one x-row each. All summary flags are written directly (no atomics/init).
// ---------------------------------------------------------------------------
__global__ __launch_bounds__(256) void pack_kernel(const float* __restrict__ W,
                                                   const float* __restrict__ x) {
    __shared__ uint32_t sm_red[8][32];   // pack_w: per-warp per-rule partial OR
    __shared__ uint32_t sm_ok[8];        // pack_x: per-warp all-ones flag
    int wi   = threadIdx.x >> 5;
    int lane = threadIdx.x & 31;

    if (blockIdx.x < WBLOCKS) {
        // ---- pack W: block owns 32 rules x 1024 k-values (one split) ----
        int s     = blockIdx.x;
        int split = s & (NSPLIT - 1);
        int r0    = (s >> 2) * 32;        // s / NSPLIT * 32
        int r     = r0 + lane;            // lanes across rules -> coalesced
        uint32_t acc = 0;
#pragma unroll
        for (int t = 0; t < 4; t++) {
            int w = split * 32 + t * 8 + wi;
            const float* p = W + (size_t)(w * 32) * N_RULES + r;
            uint32_t word = 0;
#pragma unroll
            for (int j = 0; j < 32; j++) {
                if (p[(size_t)j * N_RULES] > 0.5f) word |= (1u << j);
            }
            g_wbits[r * KWORDS + w] = word;
            acc |= word;
        }
        sm_red[wi][lane] = acc;
        __syncthreads();
        if (wi == 0) {
            uint32_t o = sm_red[0][lane] | sm_red[1][lane] | sm_red[2][lane] |
                         sm_red[3][lane] | sm_red[4][lane] | sm_red[5][lane] |
                         sm_red[6][lane] | sm_red[7][lane];
            g_wany4[split * N_RULES + r] = o;
        }
    } else {
        // ---- pack x: block owns one row; warp owns 512 consecutive elems ----
        int b = blockIdx.x - WBLOCKS;
        const float* px = x + (size_t)b * IN_DIM + wi * 512;
        uint32_t wrd[16];
        uint32_t ones = 0xFFFFFFFFu;
#pragma unroll
        for (int u = 0; u < 16; u++) {
            float v = px[u * 32 + lane];                 // coalesced 128B line
            wrd[u] = __ballot_sync(0xFFFFFFFFu, v != 1.0f);
            ones &= wrd[u];
        }
        if (lane == 0) {
            uint4* q = reinterpret_cast<uint4*>(g_abits + b * KWORDS + wi * 16);
            q[0] = make_uint4(wrd[0],  wrd[1],  wrd[2],  wrd[3]);
            q[1] = make_uint4(wrd[4],  wrd[5],  wrd[6],  wrd[7]);
            q[2] = make_uint4(wrd[8],  wrd[9],  wrd[10], wrd[11]);
            q[3] = make_uint4(wrd[12], wrd[13], wrd[14], wrd[15]);
            sm_ok[wi] = (ones == 0xFFFFFFFFu) ? 1u : 0u;
        }
        __syncthreads();
        if (threadIdx.x == 0) {
            uint32_t a = sm_ok[0] & sm_ok[1] & sm_ok[2] & sm_ok[3] &
                         sm_ok[4] & sm_ok[5] & sm_ok[6] & sm_ok[7];
            g_aflag[b] = a ? 0u : 1u;   // 1 <=> row has an exact 1.0
        }
    }
}

// Rare general path: any weight-selected k with x[b,k] != 1 makes res > 0.
__device__ __forceinline__ float conj_general(int b, int r) {
    const uint32_t* A  = g_abits + b * KWORDS;
    const uint32_t* Wp = g_wbits + r * KWORDS;
    for (int i = 0; i < KWORDS; i++) {
        if (A[i] & Wp[i]) return 0.0f;
    }
    return 1.0f;
}

// ---------------------------------------------------------------------------
// Output [BATCH, N_RULES] f32, float4-vectorized (4 rules/thread).
// wany = OR over the 4 k-split partials (L1-resident 32KB table).
// ---------------------------------------------------------------------------
__global__ __launch_bounds__(256) void out_kernel(float* __restrict__ out) {
    int idx = blockIdx.x * blockDim.x + threadIdx.x;   // [0, BATCH*512)
    int b = idx >> 9;
    int g = idx & 511;
    const uint4* W4 = reinterpret_cast<const uint4*>(g_wany4);
    uint4 a0 = W4[g];
    uint4 a1 = W4[512  + g];
    uint4 a2 = W4[1024 + g];
    uint4 a3 = W4[1536 + g];
    uint4 w4;
    w4.x = a0.x | a1.x | a2.x | a3.x;
    w4.y = a0.y | a1.y | a2.y | a3.y;
    w4.z = a0.z | a1.z | a2.z | a3.z;
    w4.w = a0.w | a1.w | a2.w | a3.w;

    float4 o;
    if ((w4.x | w4.y | w4.z | w4.w) == 0u) {
        o = make_float4(1.0f, 1.0f, 1.0f, 1.0f);        // empty rules -> 1
    } else if (!g_aflag[b]) {
        o.x = (w4.x == 0u) ? 1.0f : 0.0f;
        o.y = (w4.y == 0u) ? 1.0f : 0.0f;
        o.z = (w4.z == 0u) ? 1.0f : 0.0f;
        o.w = (w4.w == 0u) ? 1.0f : 0.0f;
    } else {
        int r0 = g * 4;
        o.x = (w4.x == 0u) ? 1.0f : conj_general(b, r0 + 0);
        o.y = (w4.y == 0u) ? 1.0f : conj_general(b, r0 + 1);
        o.z = (w4.z == 0u) ? 1.0f : conj_general(b, r0 + 2);
        o.w = (w4.w == 0u) ? 1.0f : conj_general(b, r0 + 3);
    }
    reinterpret_cast<float4*>(out)[idx] = o;
}

// ---------------------------------------------------------------------------
extern "C" void kernel_launch(void* const* d_in, const int* in_sizes, int n_in,
                              void* d_out, int out_size) {
    const float* x = (const float*)d_in[0];   // [BATCH, IN_DIM]
    const float* W = (const float*)d_in[1];   // [IN_DIM, N_RULES]
    float* out = (float*)d_out;               // [BATCH, N_RULES]

    (void)in_sizes; (void)n_in; (void)out_size;

    pack_kernel<<<WBLOCKS + BATCH, 256>>>(W, x);          // 8448 blocks
    out_kernel<<<(BATCH * 512) / 256, 256>>>(out);        // 16384 blocks
}

// round 4
// speedup vs baseline: 2.2668x; 1.0359x over previous
#include <cuda_runtime.h>
#include <stdint.h>

// Problem shape (fixed by the dataset)
#define BATCH   8192
#define IN_DIM  4096
#define N_RULES 2048
#define KWORDS  (IN_DIM / 32)     // 128 u32 bit-words along k
#define NSPLIT  4                 // k-splits for pack_w (wany partials)
#define WBLOCKS (NSPLIT * (N_RULES / 32))   // 256 pack_w blocks
#define ROWS_PB 16                // rows per out-block

// Scratch (device globals — no allocation allowed)
__device__ uint32_t g_wbits[N_RULES * KWORDS];     // [r][w]
__device__ uint32_t g_abits[BATCH   * KWORDS];     // [b][w]
__device__ uint32_t g_wany4[NSPLIT * N_RULES];     // per-split OR of rule words
__device__ uint32_t g_aflag[BATCH];                // 1 if row b has any exact x==1.0f

// ---------------------------------------------------------------------------
// Fused pack kernel. Blocks [0, WBLOCKS) pack W; blocks [WBLOCKS, +BATCH) pack
// one x-row each. All summary flags written directly (no atomics, no init).
// ---------------------------------------------------------------------------
__global__ __launch_bounds__(256) void pack_kernel(const float* __restrict__ W,
                                                   const float* __restrict__ x) {
    __shared__ uint32_t sm_red[8][32];   // pack_w: per-warp per-rule partial OR
    __shared__ uint32_t sm_ok[8];        // pack_x: per-warp all-ones flag
    int wi   = threadIdx.x >> 5;
    int lane = threadIdx.x & 31;

    if (blockIdx.x < WBLOCKS) {
        // ---- pack W: block owns 32 rules x 1024 k-values (one split) ----
        int s     = blockIdx.x;
        int split = s & (NSPLIT - 1);
        int r     = (s >> 2) * 32 + lane;   // lanes across rules -> coalesced
        uint32_t acc = 0;
#pragma unroll
        for (int t = 0; t < 4; t++) {
            int w = split * 32 + t * 8 + wi;
            const float* p = W + (size_t)(w * 32) * N_RULES + r;
            uint32_t word = 0;
#pragma unroll
            for (int j = 0; j < 32; j++) {
                if (p[(size_t)j * N_RULES] > 0.5f) word |= (1u << j);
            }
            g_wbits[r * KWORDS + w] = word;
            acc |= word;
        }
        sm_red[wi][lane] = acc;
        __syncthreads();
        if (wi == 0) {
            uint32_t o = sm_red[0][lane] | sm_red[1][lane] | sm_red[2][lane] |
                         sm_red[3][lane] | sm_red[4][lane] | sm_red[5][lane] |
                         sm_red[6][lane] | sm_red[7][lane];
            g_wany4[split * N_RULES + r] = o;
        }
    } else {
        // ---- pack x: block owns one row; warp owns 512 consecutive elems ----
        int b = blockIdx.x - WBLOCKS;
        const float* px = x + (size_t)b * IN_DIM + wi * 512;
        uint32_t wrd[16];
        uint32_t ones = 0xFFFFFFFFu;
#pragma unroll
        for (int u = 0; u < 16; u++) {
            float v = px[u * 32 + lane];                 // coalesced 128B line
            wrd[u] = __ballot_sync(0xFFFFFFFFu, v != 1.0f);
            ones &= wrd[u];
        }
        if (lane == 0) {
            uint4* q = reinterpret_cast<uint4*>(g_abits + b * KWORDS + wi * 16);
            q[0] = make_uint4(wrd[0],  wrd[1],  wrd[2],  wrd[3]);
            q[1] = make_uint4(wrd[4],  wrd[5],  wrd[6],  wrd[7]);
            q[2] = make_uint4(wrd[8],  wrd[9],  wrd[10], wrd[11]);
            q[3] = make_uint4(wrd[12], wrd[13], wrd[14], wrd[15]);
            sm_ok[wi] = (ones == 0xFFFFFFFFu) ? 1u : 0u;
        }
        __syncthreads();
        if (threadIdx.x == 0) {
            uint32_t a = sm_ok[0] & sm_ok[1] & sm_ok[2] & sm_ok[3] &
                         sm_ok[4] & sm_ok[5] & sm_ok[6] & sm_ok[7];
            g_aflag[b] = a ? 0u : 1u;   // 1 <=> row has an exact 1.0
        }
    }
}

// Rare general path: any weight-selected k with x[b,k] != 1 makes res > 0.
__device__ __forceinline__ float conj_general(int b, int r) {
    const uint32_t* A  = g_abits + b * KWORDS;
    const uint32_t* Wp = g_wbits + r * KWORDS;
    for (int i = 0; i < KWORDS; i++) {
        if (A[i] & Wp[i]) return 0.0f;
    }
    return 1.0f;
}

// ---------------------------------------------------------------------------
// Output kernel, transposed mapping: each thread owns ONE 4-rule group g,
// folds wany partials once into registers, precomputes the aflag==0 answer,
// then streams ROWS_PB rows. L1 read traffic ~64x lower than per-row reads.
// Grid: (N_RULES/4/256) x (BATCH/ROWS_PB) = 2 x 512 = 1024 blocks.
// ---------------------------------------------------------------------------
__global__ __launch_bounds__(256) void out_kernel(float* __restrict__ out) {
    int g  = (blockIdx.x & 1) * 256 + threadIdx.x;       // group in [0, 512)
    int b0 = (blockIdx.x >> 1) * ROWS_PB;
    int lane = threadIdx.x & 31;

    const uint4* W4 = reinterpret_cast<const uint4*>(g_wany4);
    uint4 a0 = W4[g];
    uint4 a1 = W4[512  + g];
    uint4 a2 = W4[1024 + g];
    uint4 a3 = W4[1536 + g];
    uint4 w4;
    w4.x = a0.x | a1.x | a2.x | a3.x;
    w4.y = a0.y | a1.y | a2.y | a3.y;
    w4.z = a0.z | a1.z | a2.z | a3.z;
    w4.w = a0.w | a1.w | a2.w | a3.w;
    bool empty = (w4.x | w4.y | w4.z | w4.w) == 0u;

    // aflag==0 answer (equals all-ones when the group is empty)
    float4 val0;
    val0.x = (w4.x == 0u) ? 1.0f : 0.0f;
    val0.y = (w4.y == 0u) ? 1.0f : 0.0f;
    val0.z = (w4.z == 0u) ? 1.0f : 0.0f;
    val0.w = (w4.w == 0u) ? 1.0f : 0.0f;

    // fetch the block's ROWS_PB aflags with one lane-parallel load
    uint32_t af_l = (lane < ROWS_PB) ? g_aflag[b0 + lane] : 0u;

    float4* o4 = reinterpret_cast<float4*>(out) + (size_t)b0 * 512 + g;
#pragma unroll
    for (int r = 0; r < ROWS_PB; r++) {
        uint32_t afr = __shfl_sync(0xFFFFFFFFu, af_l, r);
        float4 o;
        if (!afr || empty) {
            o = val0;                         // dominant path
        } else {
            int b  = b0 + r;
            int r0 = g * 4;
            o.x = (w4.x == 0u) ? 1.0f : conj_general(b, r0 + 0);
            o.y = (w4.y == 0u) ? 1.0f : conj_general(b, r0 + 1);
            o.z = (w4.z == 0u) ? 1.0f : conj_general(b, r0 + 2);
            o.w = (w4.w == 0u) ? 1.0f : conj_general(b, r0 + 3);
        }
        o4[(size_t)r * 512] = o;
    }
}

// ---------------------------------------------------------------------------
extern "C" void kernel_launch(void* const* d_in, const int* in_sizes, int n_in,
                              void* d_out, int out_size) {
    const float* x = (const float*)d_in[0];   // [BATCH, IN_DIM]
    const float* W = (const float*)d_in[1];   // [IN_DIM, N_RULES]
    float* out = (float*)d_out;               // [BATCH, N_RULES]

    (void)in_sizes; (void)n_in; (void)out_size;

    pack_kernel<<<WBLOCKS + BATCH, 256>>>(W, x);                  // 8448 blocks
    out_kernel<<<2 * (BATCH / ROWS_PB), 256>>>(out);              // 1024 blocks
}

// round 5
// speedup vs baseline: 3.6209x; 1.5973x over previous
#include <cuda_runtime.h>
#include <stdint.h>

// Problem shape (fixed by the dataset)
#define BATCH   8192
#define IN_DIM  4096
#define N_RULES 2048
#define KWORDS  (IN_DIM / 32)     // 128 u32 bit-words along k
#define NSPLIT  4                 // k-splits for pack_w (wany partials)
#define WBLOCKS (NSPLIT * (N_RULES / 32))   // 256 pack_w blocks
#define ROWS_PB 16                // rows per out-block

// Scratch (device globals — no allocation allowed)
__device__ uint32_t g_wbits[N_RULES * KWORDS];     // [r][w]
__device__ uint32_t g_abits[BATCH   * KWORDS];     // [b][w]
__device__ uint32_t g_wany4[NSPLIT * N_RULES];     // per-split OR of rule words
__device__ uint32_t g_aflag[BATCH];                // 1 if row b has any exact x==1.0f
__device__ uint32_t g_rsum [WBLOCKS];              // per-pack_w-block OR summary
                                                   // (always written -> no init)

// ---------------------------------------------------------------------------
// Kernel 1: pack W > 0.5. Block owns 32 rules x 1024 k-values (one split).
// Writes g_wbits, g_wany4, and its g_rsum summary word (no atomics).
// ---------------------------------------------------------------------------
__global__ __launch_bounds__(256) void pack_w_kernel(const float* __restrict__ W) {
    __shared__ uint32_t sm_red[8][32];
    int wi   = threadIdx.x >> 5;
    int lane = threadIdx.x & 31;

    int s     = blockIdx.x;
    int split = s & (NSPLIT - 1);
    int r     = (s >> 2) * 32 + lane;     // lanes across rules -> coalesced
    uint32_t acc = 0;
#pragma unroll
    for (int t = 0; t < 4; t++) {
        int w = split * 32 + t * 8 + wi;
        const float* p = W + (size_t)(w * 32) * N_RULES + r;
        uint32_t word = 0;
#pragma unroll
        for (int j = 0; j < 32; j++) {
            if (p[(size_t)j * N_RULES] > 0.5f) word |= (1u << j);
        }
        g_wbits[r * KWORDS + w] = word;
        acc |= word;
    }
    sm_red[wi][lane] = acc;
    __syncthreads();
    if (wi == 0) {
        uint32_t o = sm_red[0][lane] | sm_red[1][lane] | sm_red[2][lane] |
                     sm_red[3][lane] | sm_red[4][lane] | sm_red[5][lane] |
                     sm_red[6][lane] | sm_red[7][lane];
        g_wany4[split * N_RULES + r] = o;
        uint32_t blk = __reduce_or_sync(0xFFFFFFFFu, o);
        if (lane == 0) g_rsum[s] = blk;   // always written each replay
    }
}

// ---------------------------------------------------------------------------
// Kernel 2: pack x. EARLY EXIT: if every rule is empty (all g_rsum == 0),
// abits/aflag can never be consumed by out_kernel, so skip the 128MB read.
// Otherwise: block owns one row; warp packs 512 consecutive elems via ballot.
// ---------------------------------------------------------------------------
__global__ __launch_bounds__(256) void pack_x_kernel(const float* __restrict__ x) {
    uint32_t rs = g_rsum[threadIdx.x];                 // WBLOCKS == blockDim.x
    if (!__syncthreads_or(rs != 0u)) return;           // dominant: all empty

    __shared__ uint32_t sm_ok[8];
    int wi   = threadIdx.x >> 5;
    int lane = threadIdx.x & 31;
    int b = blockIdx.x;
    const float* px = x + (size_t)b * IN_DIM + wi * 512;
    uint32_t wrd[16];
    uint32_t ones = 0xFFFFFFFFu;
#pragma unroll
    for (int u = 0; u < 16; u++) {
        float v = px[u * 32 + lane];                   // coalesced 128B line
        wrd[u] = __ballot_sync(0xFFFFFFFFu, v != 1.0f);
        ones &= wrd[u];
    }
    if (lane == 0) {
        uint4* q = reinterpret_cast<uint4*>(g_abits + b * KWORDS + wi * 16);
        q[0] = make_uint4(wrd[0],  wrd[1],  wrd[2],  wrd[3]);
        q[1] = make_uint4(wrd[4],  wrd[5],  wrd[6],  wrd[7]);
        q[2] = make_uint4(wrd[8],  wrd[9],  wrd[10], wrd[11]);
        q[3] = make_uint4(wrd[12], wrd[13], wrd[14], wrd[15]);
        sm_ok[wi] = (ones == 0xFFFFFFFFu) ? 1u : 0u;
    }
    __syncthreads();
    if (threadIdx.x == 0) {
        uint32_t a = sm_ok[0] & sm_ok[1] & sm_ok[2] & sm_ok[3] &
                     sm_ok[4] & sm_ok[5] & sm_ok[6] & sm_ok[7];
        g_aflag[b] = a ? 0u : 1u;                      // 1 <=> row has exact 1.0
    }
}

// Rare general path: any weight-selected k with x[b,k] != 1 makes res > 0.
__device__ __forceinline__ float conj_general(int b, int r) {
    const uint32_t* A  = g_abits + b * KWORDS;
    const uint32_t* Wp = g_wbits + r * KWORDS;
    for (int i = 0; i < KWORDS; i++) {
        if (A[i] & Wp[i]) return 0.0f;
    }
    return 1.0f;
}

// ---------------------------------------------------------------------------
// Kernel 3: output [BATCH, N_RULES]. Thread owns one 4-rule group, folds wany
// partials into registers once, streams ROWS_PB rows of coalesced float4.
// aflag/abits are read ONLY when the group is non-empty (=> pack_x ran fully).
// ---------------------------------------------------------------------------
__global__ __launch_bounds__(256) void out_kernel(float* __restrict__ out) {
    int g  = (blockIdx.x & 1) * 256 + threadIdx.x;     // group in [0, 512)
    int b0 = (blockIdx.x >> 1) * ROWS_PB;
    int lane = threadIdx.x & 31;

    const uint4* W4 = reinterpret_cast<const uint4*>(g_wany4);
    uint4 a0 = W4[g];
    uint4 a1 = W4[512  + g];
    uint4 a2 = W4[1024 + g];
    uint4 a3 = W4[1536 + g];
    uint4 w4;
    w4.x = a0.x | a1.x | a2.x | a3.x;
    w4.y = a0.y | a1.y | a2.y | a3.y;
    w4.z = a0.z | a1.z | a2.z | a3.z;
    w4.w = a0.w | a1.w | a2.w | a3.w;
    bool empty = (w4.x | w4.y | w4.z | w4.w) == 0u;

    float4 val0;
    val0.x = (w4.x == 0u) ? 1.0f : 0.0f;
    val0.y = (w4.y == 0u) ? 1.0f : 0.0f;
    val0.z = (w4.z == 0u) ? 1.0f : 0.0f;
    val0.w = (w4.w == 0u) ? 1.0f : 0.0f;

    // fetch the block's ROWS_PB aflags only if some rule in flight is nonempty
    uint32_t af_l = 0u;
    if (!empty && lane < ROWS_PB) af_l = g_aflag[b0 + lane];

    float4* o4 = reinterpret_cast<float4*>(out) + (size_t)b0 * 512 + g;
#pragma unroll
    for (int r = 0; r < ROWS_PB; r++) {
        uint32_t afr = __shfl_sync(0xFFFFFFFFu, af_l, r);
        float4 o;
        if (empty || !afr) {
            o = val0;                                  // dominant path
        } else {
            int b  = b0 + r;
            int r0 = g * 4;
            o.x = (w4.x == 0u) ? 1.0f : conj_general(b, r0 + 0);
            o.y = (w4.y == 0u) ? 1.0f : conj_general(b, r0 + 1);
            o.z = (w4.z == 0u) ? 1.0f : conj_general(b, r0 + 2);
            o.w = (w4.w == 0u) ? 1.0f : conj_general(b, r0 + 3);
        }
        o4[(size_t)r * 512] = o;
    }
}

// ---------------------------------------------------------------------------
extern "C" void kernel_launch(void* const* d_in, const int* in_sizes, int n_in,
                              void* d_out, int out_size) {
    const float* x = (const float*)d_in[0];   // [BATCH, IN_DIM]
    const float* W = (const float*)d_in[1];   // [IN_DIM, N_RULES]
    float* out = (float*)d_out;               // [BATCH, N_RULES]

    (void)in_sizes; (void)n_in; (void)out_size;

    pack_w_kernel<<<WBLOCKS, 256>>>(W);               // 256 blocks
    pack_x_kernel<<<BATCH, 256>>>(x);                 // 8192 blocks (early-exit)
    out_kernel<<<2 * (BATCH / ROWS_PB), 256>>>(out);  // 1024 blocks
}